// round 5
// baseline (speedup 1.0000x reference)
#include <cuda_runtime.h>
#include <math.h>

#define N_NODES  50000
#define N_EDGES  800000
#define IN_FEATS 256
#define H_FEATS  64
#define NEG_SLOPE 0.01f

// ---------------- scratch (static __device__, no allocations) ----------------
// f_k = P^k h for k = 0..6 ; 7 * 50000 * 64 floats = 89.6 MB
__device__ __align__(16) float g_F[7][N_NODES * H_FEATS];
__device__ int   g_cnt[N_NODES];        // in-degree (by dst) histogram for CSR
__device__ int   g_deg[N_NODES];        // out-degree (by src) for d_inv
__device__ int   g_cur[N_NODES];        // scatter cursors
__device__ int   g_rowptr[N_NODES + 1]; // CSR row pointers (by dst)
__device__ int   g_col[N_EDGES];        // CSR column indices = src node per edge
__device__ float g_dinv[N_NODES];       // clip(deg,1)^-0.5

// ---------------- small helpers ----------------
__global__ void k_zero() {
    int i = blockIdx.x * blockDim.x + threadIdx.x;
    if (i < N_NODES) { g_cnt[i] = 0; g_deg[i] = 0; g_cur[i] = 0; }
}

__global__ void k_hist(const int* __restrict__ src, const int* __restrict__ dst) {
    int i = blockIdx.x * blockDim.x + threadIdx.x;
    if (i < N_EDGES) {
        atomicAdd(&g_cnt[dst[i]], 1);
        atomicAdd(&g_deg[src[i]], 1);
    }
}

__global__ void k_dinv() {
    int i = blockIdx.x * blockDim.x + threadIdx.x;
    if (i < N_NODES) {
        int d = g_deg[i];
        float df = (float)(d < 1 ? 1 : d);
        g_dinv[i] = rsqrtf(df);
    }
}

// Single-block exclusive scan of g_cnt -> g_rowptr (50000 elements, shfl-based)
__global__ void k_scan() {
    __shared__ int warpsum[32];
    __shared__ int s_carry;
    int lane = threadIdx.x & 31;
    int wid  = threadIdx.x >> 5;
    if (threadIdx.x == 0) s_carry = 0;
    __syncthreads();
    for (int base = 0; base < N_NODES; base += 1024) {
        int i = base + threadIdx.x;
        int v = (i < N_NODES) ? g_cnt[i] : 0;
        int x = v;
        #pragma unroll
        for (int o = 1; o < 32; o <<= 1) {
            int y = __shfl_up_sync(0xffffffffu, x, o);
            if (lane >= o) x += y;
        }
        if (lane == 31) warpsum[wid] = x;
        __syncthreads();
        if (wid == 0) {
            int w = warpsum[lane];
            #pragma unroll
            for (int o = 1; o < 32; o <<= 1) {
                int y = __shfl_up_sync(0xffffffffu, w, o);
                if (lane >= o) w += y;
            }
            warpsum[lane] = w;
        }
        __syncthreads();
        int prefix = s_carry + (wid > 0 ? warpsum[wid - 1] : 0);
        if (i < N_NODES) g_rowptr[i] = prefix + x - v;
        __syncthreads();
        if (threadIdx.x == 0) s_carry += warpsum[31];
        __syncthreads();
    }
    if (threadIdx.x == 0) g_rowptr[N_NODES] = s_carry;
}

__global__ void k_scatter(const int* __restrict__ src, const int* __restrict__ dst) {
    int i = blockIdx.x * blockDim.x + threadIdx.x;
    if (i < N_EDGES) {
        int d = dst[i];
        int pos = g_rowptr[d] + atomicAdd(&g_cur[d], 1);
        g_col[pos] = src[i];
    }
}

// ---------------- GEMM: h = leaky_relu(x @ W + b) -> g_F[0] ----------------
// 64 nodes x 64 feats per block, k-tile 32, 256 threads, 4x4 per thread.
__global__ __launch_bounds__(256) void k_gemm(const float* __restrict__ x,
                                              const float* __restrict__ W,
                                              const float* __restrict__ b) {
    __shared__ float xs[32][65];                 // [k][node], pitch 65 (bank-clean stores)
    __shared__ __align__(16) float ws[32][64];   // [k][feat]
    int t  = threadIdx.x;
    int tx = t & 15;   // feat group: feats tx*4 .. tx*4+3
    int ty = t >> 4;   // node group: nodes ty*4 .. ty*4+3
    int nodeBase = blockIdx.x * 64;

    float acc[4][4];
    #pragma unroll
    for (int i = 0; i < 4; i++)
        #pragma unroll
        for (int j = 0; j < 4; j++) acc[i][j] = 0.f;

    for (int k0 = 0; k0 < IN_FEATS; k0 += 32) {
        // load x tile (64 nodes x 32 k), transposed into xs[k][node]
        #pragma unroll
        for (int r = 0; r < 2; r++) {
            int idx = t + r * 256;         // 0..511 float4 slots
            int row = idx >> 3;            // node within tile 0..63
            int kq  = idx & 7;             // float4 index 0..7
            int node = nodeBase + row;
            float4 v = make_float4(0.f, 0.f, 0.f, 0.f);
            if (node < N_NODES)
                v = *(const float4*)(x + (long long)node * IN_FEATS + k0 + kq * 4);
            xs[kq * 4 + 0][row] = v.x;
            xs[kq * 4 + 1][row] = v.y;
            xs[kq * 4 + 2][row] = v.z;
            xs[kq * 4 + 3][row] = v.w;
        }
        // load W tile (32 k x 64 feats)
        #pragma unroll
        for (int r = 0; r < 2; r++) {
            int idx = t + r * 256;         // 0..511 float4 slots
            int kk = idx >> 4;             // 0..31
            int fq = idx & 15;             // 0..15
            float4 v = *(const float4*)(W + (k0 + kk) * H_FEATS + fq * 4);
            *(float4*)&ws[kk][fq * 4] = v;
        }
        __syncthreads();
        #pragma unroll
        for (int k = 0; k < 32; k++) {
            float4 wv = *(const float4*)&ws[k][tx * 4];
            float xv0 = xs[k][ty * 4 + 0];
            float xv1 = xs[k][ty * 4 + 1];
            float xv2 = xs[k][ty * 4 + 2];
            float xv3 = xs[k][ty * 4 + 3];
            acc[0][0] += xv0 * wv.x; acc[0][1] += xv0 * wv.y; acc[0][2] += xv0 * wv.z; acc[0][3] += xv0 * wv.w;
            acc[1][0] += xv1 * wv.x; acc[1][1] += xv1 * wv.y; acc[1][2] += xv1 * wv.z; acc[1][3] += xv1 * wv.w;
            acc[2][0] += xv2 * wv.x; acc[2][1] += xv2 * wv.y; acc[2][2] += xv2 * wv.z; acc[2][3] += xv2 * wv.w;
            acc[3][0] += xv3 * wv.x; acc[3][1] += xv3 * wv.y; acc[3][2] += xv3 * wv.z; acc[3][3] += xv3 * wv.w;
        }
        __syncthreads();
    }
    float4 bv = *(const float4*)(b + tx * 4);
    #pragma unroll
    for (int i = 0; i < 4; i++) {
        int node = nodeBase + ty * 4 + i;
        if (node < N_NODES) {
            float4 o;
            o.x = acc[i][0] + bv.x;
            o.y = acc[i][1] + bv.y;
            o.z = acc[i][2] + bv.z;
            o.w = acc[i][3] + bv.w;
            o.x = o.x >= 0.f ? o.x : NEG_SLOPE * o.x;
            o.y = o.y >= 0.f ? o.y : NEG_SLOPE * o.y;
            o.z = o.z >= 0.f ? o.z : NEG_SLOPE * o.z;
            o.w = o.w >= 0.f ? o.w : NEG_SLOPE * o.w;
            *(float4*)&g_F[0][node * H_FEATS + tx * 4] = o;
        }
    }
}

// ---------------- propagation: g_F[k] = P g_F[k-1] (warp per node) ----------------
__global__ __launch_bounds__(256) void k_prop(int kstep) {
    const float*  fin  = &g_F[kstep - 1][0];
    float*        fout = &g_F[kstep][0];
    int gw = (blockIdx.x * blockDim.x + threadIdx.x) >> 5;
    if (gw >= N_NODES) return;
    int lane = threadIdx.x & 31;
    const float2* __restrict__ F2 = (const float2*)fin;
    int beg = g_rowptr[gw];
    int end = g_rowptr[gw + 1];
    float ax = 0.f, ay = 0.f;
    int e = beg;
    for (; e + 4 <= end; e += 4) {
        int u0 = g_col[e + 0];
        int u1 = g_col[e + 1];
        int u2 = g_col[e + 2];
        int u3 = g_col[e + 3];
        float d0 = g_dinv[u0], d1 = g_dinv[u1], d2 = g_dinv[u2], d3 = g_dinv[u3];
        float2 f0 = F2[u0 * 32 + lane];
        float2 f1 = F2[u1 * 32 + lane];
        float2 f2v = F2[u2 * 32 + lane];
        float2 f3 = F2[u3 * 32 + lane];
        ax += d0 * f0.x; ay += d0 * f0.y;
        ax += d1 * f1.x; ay += d1 * f1.y;
        ax += d2 * f2v.x; ay += d2 * f2v.y;
        ax += d3 * f3.x; ay += d3 * f3.y;
    }
    for (; e < end; e++) {
        int u = g_col[e];
        float d = g_dinv[u];
        float2 f = F2[u * 32 + lane];
        ax += d * f.x; ay += d * f.y;
    }
    float dv = g_dinv[gw];
    float2 fv = F2[gw * 32 + lane];
    fv.x -= dv * ax;
    fv.y -= dv * ay;
    ((float2*)fout)[gw * 32 + lane] = fv;
}

// ---------------- combine: out[:, i*64+j] = sum_k theta[i][k] * f_k[:, j] ----------------
struct ThetaPack { float t[5][7]; };

__global__ __launch_bounds__(256) void k_combine(float* __restrict__ out, ThetaPack tp) {
    int idx = blockIdx.x * blockDim.x + threadIdx.x;
    if (idx >= N_NODES * H_FEATS) return;
    float f[7];
    #pragma unroll
    for (int k = 0; k < 7; k++) f[k] = g_F[k][idx];
    int node = idx >> 6;
    int j    = idx & 63;
    long long base = (long long)node * (5 * H_FEATS) + j;
    #pragma unroll
    for (int i = 0; i < 5; i++) {
        float a = 0.f;
        #pragma unroll
        for (int k = 0; k < 7; k++) a += tp.t[i][k] * f[k];
        out[base + i * H_FEATS] = a;
    }
}

// ---------------- host: theta coefficients (pure arithmetic, deterministic) ----------------
static double fact_d(int n) { double r = 1.0; for (int i = 2; i <= n; i++) r *= i; return r; }

static ThetaPack make_thetas() {
    ThetaPack tp;
    const int d = 4, OFF = 2;
    const double e = 1.4;
    for (int ii = 0; ii < 5; ii++) {
        int i = OFF + ii;                 // 2..6
        int m = d - i + OFF;              // 6-i
        // B = Gamma(i+1)*Gamma(d+1-i+OFF)/Gamma(d+2+OFF) = i!*(d-i+OFF)!/(d+1+OFF)!
        double B = fact_d(i) * fact_d(d - i + OFF) / fact_d(d + 1 + OFF);
        double c[7] = {0, 0, 0, 0, 0, 0, 0};
        double inv_e_i = pow(1.0 / e, (double)i);
        double pj = 1.0;
        for (int j = 0; j <= m; j++) {
            double comb = fact_d(m) / (fact_d(j) * fact_d(m - j));
            c[i + j] = inv_e_i * comb * pj / (e * B);
            pj *= (-1.0 / e);
        }
        for (int k = 0; k < 7; k++) tp.t[ii][k] = (float)c[k];
    }
    return tp;
}

// ---------------- entry point ----------------
extern "C" void kernel_launch(void* const* d_in, const int* in_sizes, int n_in,
                              void* d_out, int out_size) {
    (void)in_sizes; (void)n_in; (void)out_size;
    const float* x   = (const float*)d_in[0];
    const float* W   = (const float*)d_in[1];
    const float* b   = (const float*)d_in[2];
    const int*   src = (const int*)d_in[3];
    const int*   dst = (const int*)d_in[4];
    float* out = (float*)d_out;

    ThetaPack tp = make_thetas();

    // CSR build + degrees
    k_zero<<<(N_NODES + 255) / 256, 256>>>();
    k_hist<<<(N_EDGES + 255) / 256, 256>>>(src, dst);
    k_dinv<<<(N_NODES + 255) / 256, 256>>>();
    k_scan<<<1, 1024>>>();
    k_scatter<<<(N_EDGES + 255) / 256, 256>>>(src, dst);

    // h = leaky_relu(xW + b) -> g_F[0]
    k_gemm<<<(N_NODES + 63) / 64, 256>>>(x, W, b);

    // f_k = P^k h, k = 1..6 (shared across all 5 thetas)
    for (int k = 1; k <= 6; k++)
        k_prop<<<(N_NODES + 7) / 8, 256>>>(k);

    // out[:, i*64:(i+1)*64] = sum_k theta[i][k] * f_k
    k_combine<<<(N_NODES * H_FEATS + 255) / 256, 256>>>(out, tp);
}

// round 6
// speedup vs baseline: 1.1703x; 1.1703x over previous
#include <cuda_runtime.h>
#include <math.h>

#define N_NODES  50000
#define N_EDGES  800000
#define IN_FEATS 256
#define H_FEATS  64
#define NEG_SLOPE 0.01f
#define SCAN_NBLK ((N_NODES + 1023) / 1024)   // 49

// ---------------- scratch (static __device__, no allocations) ----------------
__device__ __align__(16) float g_F[7][N_NODES * H_FEATS]; // f_k = P^k h, 89.6 MB
__device__ int   g_cnt[N_NODES];
__device__ int   g_deg[N_NODES];
__device__ int   g_cur[N_NODES];
__device__ int   g_rowptr[N_NODES + 1];
__device__ int   g_col[N_EDGES];
__device__ float g_dinv[N_NODES];
__device__ int   g_bsum[64];
__device__ int   g_boff[64];

// ---------------- CSR build ----------------
__global__ void k_zero() {
    int i = blockIdx.x * blockDim.x + threadIdx.x;
    if (i < N_NODES) { g_cnt[i] = 0; g_deg[i] = 0; g_cur[i] = 0; }
}

__global__ void k_hist(const int* __restrict__ src, const int* __restrict__ dst) {
    int i = blockIdx.x * blockDim.x + threadIdx.x;
    if (i < N_EDGES) {
        atomicAdd(&g_cnt[dst[i]], 1);
        atomicAdd(&g_deg[src[i]], 1);
    }
}

__global__ void k_dinv() {
    int i = blockIdx.x * blockDim.x + threadIdx.x;
    if (i < N_NODES) {
        int d = g_deg[i];
        float df = (float)(d < 1 ? 1 : d);
        g_dinv[i] = rsqrtf(df);
    }
}

// Stage 1: per-block exclusive scan (1024 elems/block), block totals to g_bsum
__global__ __launch_bounds__(1024) void k_scan_blk() {
    __shared__ int warpsum[32];
    int i = blockIdx.x * 1024 + threadIdx.x;
    int lane = threadIdx.x & 31;
    int wid  = threadIdx.x >> 5;
    int v = (i < N_NODES) ? g_cnt[i] : 0;
    int x = v;
    #pragma unroll
    for (int o = 1; o < 32; o <<= 1) {
        int y = __shfl_up_sync(0xffffffffu, x, o);
        if (lane >= o) x += y;
    }
    if (lane == 31) warpsum[wid] = x;
    __syncthreads();
    if (wid == 0) {
        int w = warpsum[lane];
        #pragma unroll
        for (int o = 1; o < 32; o <<= 1) {
            int y = __shfl_up_sync(0xffffffffu, w, o);
            if (lane >= o) w += y;
        }
        warpsum[lane] = w;
    }
    __syncthreads();
    int prefix = (wid > 0 ? warpsum[wid - 1] : 0);
    if (i < N_NODES) g_rowptr[i] = prefix + x - v;   // exclusive within block
    if (threadIdx.x == 1023) g_bsum[blockIdx.x] = prefix + x;  // block total
}

// Stage 2: exclusive scan of 49 block totals (one block, 64 threads)
__global__ void k_scan_top() {
    __shared__ int w0sum;
    int lane = threadIdx.x & 31;
    int wid  = threadIdx.x >> 5;
    int v = (threadIdx.x < SCAN_NBLK) ? g_bsum[threadIdx.x] : 0;
    int x = v;
    #pragma unroll
    for (int o = 1; o < 32; o <<= 1) {
        int y = __shfl_up_sync(0xffffffffu, x, o);
        if (lane >= o) x += y;
    }
    if (wid == 0 && lane == 31) w0sum = x;
    __syncthreads();
    int incl = x + (wid == 1 ? w0sum : 0);
    if (threadIdx.x < SCAN_NBLK) g_boff[threadIdx.x] = incl - v;
}

// Stage 3: add block offsets
__global__ __launch_bounds__(1024) void k_scan_add() {
    int i = blockIdx.x * 1024 + threadIdx.x;
    if (i < N_NODES) g_rowptr[i] += g_boff[blockIdx.x];
    if (i == 0) g_rowptr[N_NODES] = N_EDGES;   // total is statically known
}

__global__ void k_scatter(const int* __restrict__ src, const int* __restrict__ dst) {
    int i = blockIdx.x * blockDim.x + threadIdx.x;
    if (i < N_EDGES) {
        int d = dst[i];
        int pos = g_rowptr[d] + atomicAdd(&g_cur[d], 1);
        g_col[pos] = src[i];
    }
}

// ---------------- GEMM: h = leaky_relu(x @ W + b) -> g_F[0] ----------------
// 128 nodes x 64 feats per block, k-tile 16, 256 threads, 8x4 per thread.
__global__ __launch_bounds__(256) void k_gemm(const float* __restrict__ x,
                                              const float* __restrict__ W,
                                              const float* __restrict__ b) {
    __shared__ float xs[16][132];                 // [k][node], pad 132 (2-way max on store)
    __shared__ __align__(16) float ws[16][64];    // [k][feat]
    int t  = threadIdx.x;
    int tx = t & 15;   // feats tx*4 .. tx*4+3
    int ty = t >> 4;   // nodes ty*8 .. ty*8+7
    int nodeBase = blockIdx.x * 128;

    float acc[8][4];
    #pragma unroll
    for (int i = 0; i < 8; i++)
        #pragma unroll
        for (int j = 0; j < 4; j++) acc[i][j] = 0.f;

    for (int k0 = 0; k0 < IN_FEATS; k0 += 16) {
        // x tile: 128 nodes x 16 k, transposed into xs[k][node]
        #pragma unroll
        for (int r = 0; r < 2; r++) {
            int idx = t + r * 256;     // 0..511 float4 slots
            int row = idx >> 2;        // node-in-tile 0..127
            int kq  = idx & 3;         // float4 within the 16-k row
            int node = nodeBase + row;
            float4 v = make_float4(0.f, 0.f, 0.f, 0.f);
            if (node < N_NODES)
                v = *(const float4*)(x + (size_t)node * IN_FEATS + k0 + kq * 4);
            xs[kq * 4 + 0][row] = v.x;
            xs[kq * 4 + 1][row] = v.y;
            xs[kq * 4 + 2][row] = v.z;
            xs[kq * 4 + 3][row] = v.w;
        }
        // W tile: 16 k x 64 feats (one float4 per thread)
        {
            int kk = t >> 4;
            int fq = t & 15;
            *(float4*)&ws[kk][fq * 4] = *(const float4*)(W + (size_t)(k0 + kk) * H_FEATS + fq * 4);
        }
        __syncthreads();
        #pragma unroll
        for (int k = 0; k < 16; k++) {
            float4 wv = *(const float4*)&ws[k][tx * 4];
            #pragma unroll
            for (int i = 0; i < 8; i++) {
                float xv = xs[k][ty * 8 + i];
                acc[i][0] += xv * wv.x;
                acc[i][1] += xv * wv.y;
                acc[i][2] += xv * wv.z;
                acc[i][3] += xv * wv.w;
            }
        }
        __syncthreads();
    }
    float4 bv = *(const float4*)(b + tx * 4);
    #pragma unroll
    for (int i = 0; i < 8; i++) {
        int node = nodeBase + ty * 8 + i;
        if (node < N_NODES) {
            float4 o;
            o.x = acc[i][0] + bv.x;
            o.y = acc[i][1] + bv.y;
            o.z = acc[i][2] + bv.z;
            o.w = acc[i][3] + bv.w;
            o.x = o.x >= 0.f ? o.x : NEG_SLOPE * o.x;
            o.y = o.y >= 0.f ? o.y : NEG_SLOPE * o.y;
            o.z = o.z >= 0.f ? o.z : NEG_SLOPE * o.z;
            o.w = o.w >= 0.f ? o.w : NEG_SLOPE * o.w;
            *(float4*)&g_F[0][(size_t)node * H_FEATS + tx * 4] = o;
        }
    }
}

// ---------------- propagation: g_F[k] = P g_F[k-1] (warp per node) ----------------
__global__ __launch_bounds__(256) void k_prop(int kstep) {
    const float* fin  = &g_F[kstep - 1][0];
    float*       fout = &g_F[kstep][0];
    int gw = (blockIdx.x * blockDim.x + threadIdx.x) >> 5;
    if (gw >= N_NODES) return;
    int lane = threadIdx.x & 31;
    const float2* __restrict__ F2 = (const float2*)fin;
    int beg = g_rowptr[gw];
    int end = g_rowptr[gw + 1];
    float ax = 0.f, ay = 0.f;
    int e = beg;
    for (; e + 4 <= end; e += 4) {
        int u0 = g_col[e + 0];
        int u1 = g_col[e + 1];
        int u2 = g_col[e + 2];
        int u3 = g_col[e + 3];
        float d0 = g_dinv[u0], d1 = g_dinv[u1], d2 = g_dinv[u2], d3 = g_dinv[u3];
        float2 f0 = F2[u0 * 32 + lane];
        float2 f1 = F2[u1 * 32 + lane];
        float2 f2v = F2[u2 * 32 + lane];
        float2 f3 = F2[u3 * 32 + lane];
        ax += d0 * f0.x;  ay += d0 * f0.y;
        ax += d1 * f1.x;  ay += d1 * f1.y;
        ax += d2 * f2v.x; ay += d2 * f2v.y;
        ax += d3 * f3.x;  ay += d3 * f3.y;
    }
    for (; e < end; e++) {
        int u = g_col[e];
        float d = g_dinv[u];
        float2 f = F2[u * 32 + lane];
        ax += d * f.x; ay += d * f.y;
    }
    float dv = g_dinv[gw];
    float2 fv = F2[gw * 32 + lane];
    fv.x -= dv * ax;
    fv.y -= dv * ay;
    ((float2*)fout)[gw * 32 + lane] = fv;
}

// ---------------- combine (float4): out[:, i*64+j] = sum_k theta[i][k] * f_k[:, j] ----
struct ThetaPack { float t[5][7]; };

__global__ __launch_bounds__(256) void k_combine(float* __restrict__ out, ThetaPack tp) {
    int idx = blockIdx.x * blockDim.x + threadIdx.x;   // over N_NODES*16 float4s
    if (idx >= N_NODES * 16) return;
    float4 f[7];
    #pragma unroll
    for (int k = 0; k < 7; k++) f[k] = ((const float4*)g_F[k])[idx];
    int node = idx >> 4;
    int j4   = idx & 15;
    float4* ob = (float4*)out + (size_t)node * 80 + j4;   // 5*64 floats = 80 float4 per node
    #pragma unroll
    for (int i = 0; i < 5; i++) {
        float4 a = make_float4(0.f, 0.f, 0.f, 0.f);
        #pragma unroll
        for (int k = 0; k < 7; k++) {
            float c = tp.t[i][k];
            a.x += c * f[k].x; a.y += c * f[k].y;
            a.z += c * f[k].z; a.w += c * f[k].w;
        }
        ob[i * 16] = a;
    }
}

// ---------------- host: theta coefficients ----------------
static double fact_d(int n) { double r = 1.0; for (int i = 2; i <= n; i++) r *= i; return r; }

static ThetaPack make_thetas() {
    ThetaPack tp;
    const int d = 4, OFF = 2;
    const double e = 1.4;
    for (int ii = 0; ii < 5; ii++) {
        int i = OFF + ii;
        int m = d - i + OFF;
        double B = fact_d(i) * fact_d(d - i + OFF) / fact_d(d + 1 + OFF);
        double c[7] = {0, 0, 0, 0, 0, 0, 0};
        double inv_e_i = pow(1.0 / e, (double)i);
        double pj = 1.0;
        for (int j = 0; j <= m; j++) {
            double comb = fact_d(m) / (fact_d(j) * fact_d(m - j));
            c[i + j] = inv_e_i * comb * pj / (e * B);
            pj *= (-1.0 / e);
        }
        for (int k = 0; k < 7; k++) tp.t[ii][k] = (float)c[k];
    }
    return tp;
}

// ---------------- entry point ----------------
extern "C" void kernel_launch(void* const* d_in, const int* in_sizes, int n_in,
                              void* d_out, int out_size) {
    (void)in_sizes; (void)n_in; (void)out_size;
    const float* x   = (const float*)d_in[0];
    const float* W   = (const float*)d_in[1];
    const float* b   = (const float*)d_in[2];
    const int*   src = (const int*)d_in[3];
    const int*   dst = (const int*)d_in[4];
    float* out = (float*)d_out;

    ThetaPack tp = make_thetas();

    // CSR build + degrees
    k_zero<<<(N_NODES + 255) / 256, 256>>>();
    k_hist<<<(N_EDGES + 255) / 256, 256>>>(src, dst);
    k_dinv<<<(N_NODES + 255) / 256, 256>>>();
    k_scan_blk<<<SCAN_NBLK, 1024>>>();
    k_scan_top<<<1, 64>>>();
    k_scan_add<<<SCAN_NBLK, 1024>>>();
    k_scatter<<<(N_EDGES + 255) / 256, 256>>>(src, dst);

    // h = leaky_relu(xW + b) -> g_F[0]
    k_gemm<<<(N_NODES + 127) / 128, 256>>>(x, W, b);

    // f_k = P^k h, k = 1..6 (shared across all 5 thetas)
    for (int k = 1; k <= 6; k++)
        k_prop<<<(N_NODES + 7) / 8, 256>>>(k);

    // out[:, i*64:(i+1)*64] = sum_k theta[i][k] * f_k
    k_combine<<<(N_NODES * 16 + 255) / 256, 256>>>(out, tp);
}

// round 9
// speedup vs baseline: 1.2273x; 1.0488x over previous
#include <cuda_runtime.h>
#include <math.h>

#define N_NODES  50000
#define N_EDGES  800000
#define IN_FEATS 256
#define H_FEATS  64
#define NEG_SLOPE 0.01f
#define SCAN_NBLK ((N_NODES + 1023) / 1024)   // 49

// ---------------- scratch (static __device__, no allocations) ----------------
__device__ __align__(16) float g_F[6][N_NODES * H_FEATS];  // f_k fp32, k=0..5 (76.8 MB)
__device__ int   g_cnt[N_NODES];
__device__ int   g_deg[N_NODES];
__device__ int   g_cur[N_NODES];
__device__ int   g_rowptr[N_NODES + 1];
__device__ int   g_col[N_EDGES];
__device__ float g_dinv[N_NODES];
__device__ int   g_bsum[64];
__device__ int   g_boff[64];

struct ThetaPack { float t[5][7]; };

// ---------------- CSR build ----------------
__global__ void k_zero() {
    int i = blockIdx.x * blockDim.x + threadIdx.x;
    if (i < N_NODES) { g_cnt[i] = 0; g_deg[i] = 0; g_cur[i] = 0; }
}

__global__ void k_hist(const int* __restrict__ src, const int* __restrict__ dst) {
    int i = blockIdx.x * blockDim.x + threadIdx.x;
    if (i < N_EDGES) {
        atomicAdd(&g_cnt[dst[i]], 1);
        atomicAdd(&g_deg[src[i]], 1);
    }
}

// Stage 1: per-block exclusive scan (1024 elems/block), block totals to g_bsum
__global__ __launch_bounds__(1024) void k_scan_blk() {
    __shared__ int warpsum[32];
    int i = blockIdx.x * 1024 + threadIdx.x;
    int lane = threadIdx.x & 31;
    int wid  = threadIdx.x >> 5;
    int v = (i < N_NODES) ? g_cnt[i] : 0;
    int x = v;
    #pragma unroll
    for (int o = 1; o < 32; o <<= 1) {
        int y = __shfl_up_sync(0xffffffffu, x, o);
        if (lane >= o) x += y;
    }
    if (lane == 31) warpsum[wid] = x;
    __syncthreads();
    if (wid == 0) {
        int w = warpsum[lane];
        #pragma unroll
        for (int o = 1; o < 32; o <<= 1) {
            int y = __shfl_up_sync(0xffffffffu, w, o);
            if (lane >= o) w += y;
        }
        warpsum[lane] = w;
    }
    __syncthreads();
    int prefix = (wid > 0 ? warpsum[wid - 1] : 0);
    if (i < N_NODES) g_rowptr[i] = prefix + x - v;
    if (threadIdx.x == 1023) g_bsum[blockIdx.x] = prefix + x;
}

// Stage 2: exclusive scan of 49 block totals
__global__ void k_scan_top() {
    __shared__ int w0sum;
    int lane = threadIdx.x & 31;
    int wid  = threadIdx.x >> 5;
    int v = (threadIdx.x < SCAN_NBLK) ? g_bsum[threadIdx.x] : 0;
    int x = v;
    #pragma unroll
    for (int o = 1; o < 32; o <<= 1) {
        int y = __shfl_up_sync(0xffffffffu, x, o);
        if (lane >= o) x += y;
    }
    if (wid == 0 && lane == 31) w0sum = x;
    __syncthreads();
    int incl = x + (wid == 1 ? w0sum : 0);
    if (threadIdx.x < SCAN_NBLK) g_boff[threadIdx.x] = incl - v;
}

// Stage 3: add block offsets + compute d_inv (deg is final after k_hist)
__global__ __launch_bounds__(1024) void k_scan_add() {
    int i = blockIdx.x * 1024 + threadIdx.x;
    if (i < N_NODES) {
        g_rowptr[i] += g_boff[blockIdx.x];
        int d = g_deg[i];
        g_dinv[i] = rsqrtf((float)(d < 1 ? 1 : d));
    }
    if (i == 0) g_rowptr[N_NODES] = N_EDGES;
}

__global__ void k_scatter(const int* __restrict__ src, const int* __restrict__ dst) {
    int i = blockIdx.x * blockDim.x + threadIdx.x;
    if (i < N_EDGES) {
        int d = dst[i];
        int pos = g_rowptr[d] + atomicAdd(&g_cur[d], 1);
        g_col[pos] = src[i];
    }
}

// ---------------- GEMM: h = leaky_relu(x @ W + b) -> g_F[0] ----------------
// 128 nodes x 64 feats per block, k-tile 16, 256 threads, 8x4 per thread.
__global__ __launch_bounds__(256) void k_gemm(const float* __restrict__ x,
                                              const float* __restrict__ W,
                                              const float* __restrict__ b) {
    __shared__ __align__(16) float xs[16][132];
    __shared__ __align__(16) float ws[16][64];
    int t  = threadIdx.x;
    int tx = t & 15;   // feats tx*4 .. tx*4+3
    int ty = t >> 4;   // nodes ty*8 .. ty*8+7
    int nodeBase = blockIdx.x * 128;

    float acc[8][4];
    #pragma unroll
    for (int i = 0; i < 8; i++)
        #pragma unroll
        for (int j = 0; j < 4; j++) acc[i][j] = 0.f;

    for (int k0 = 0; k0 < IN_FEATS; k0 += 16) {
        #pragma unroll
        for (int r = 0; r < 2; r++) {
            int idx = t + r * 256;
            int row = idx >> 2;
            int kq  = idx & 3;
            int node = nodeBase + row;
            float4 v = make_float4(0.f, 0.f, 0.f, 0.f);
            if (node < N_NODES)
                v = *(const float4*)(x + (size_t)node * IN_FEATS + k0 + kq * 4);
            xs[kq * 4 + 0][row] = v.x;
            xs[kq * 4 + 1][row] = v.y;
            xs[kq * 4 + 2][row] = v.z;
            xs[kq * 4 + 3][row] = v.w;
        }
        {
            int kk = t >> 4;
            int fq = t & 15;
            *(float4*)&ws[kk][fq * 4] = *(const float4*)(W + (size_t)(k0 + kk) * H_FEATS + fq * 4);
        }
        __syncthreads();
        #pragma unroll
        for (int k = 0; k < 16; k++) {
            float4 wv  = *(const float4*)&ws[k][tx * 4];
            float4 xv0 = *(const float4*)&xs[k][ty * 8];
            float4 xv1 = *(const float4*)&xs[k][ty * 8 + 4];
            float xv[8] = {xv0.x, xv0.y, xv0.z, xv0.w, xv1.x, xv1.y, xv1.z, xv1.w};
            #pragma unroll
            for (int i = 0; i < 8; i++) {
                acc[i][0] += xv[i] * wv.x;
                acc[i][1] += xv[i] * wv.y;
                acc[i][2] += xv[i] * wv.z;
                acc[i][3] += xv[i] * wv.w;
            }
        }
        __syncthreads();
    }
    float4 bv = *(const float4*)(b + tx * 4);
    #pragma unroll
    for (int i = 0; i < 8; i++) {
        int node = nodeBase + ty * 8 + i;
        if (node < N_NODES) {
            float4 o;
            o.x = acc[i][0] + bv.x;
            o.y = acc[i][1] + bv.y;
            o.z = acc[i][2] + bv.z;
            o.w = acc[i][3] + bv.w;
            o.x = o.x >= 0.f ? o.x : NEG_SLOPE * o.x;
            o.y = o.y >= 0.f ? o.y : NEG_SLOPE * o.y;
            o.z = o.z >= 0.f ? o.z : NEG_SLOPE * o.z;
            o.w = o.w >= 0.f ? o.w : NEG_SLOPE * o.w;
            *(float4*)&g_F[0][(size_t)node * H_FEATS + tx * 4] = o;
        }
    }
}

// ---------------- propagation (fp32 gather, warp per node) ----------------
__device__ __forceinline__ void prop_accum(int beg, int end, int lane,
                                           const float2* __restrict__ F2,
                                           float& ax, float& ay) {
    int e = beg;
    for (; e + 4 <= end; e += 4) {
        int u0 = g_col[e + 0];
        int u1 = g_col[e + 1];
        int u2 = g_col[e + 2];
        int u3 = g_col[e + 3];
        float d0 = g_dinv[u0], d1 = g_dinv[u1], d2 = g_dinv[u2], d3 = g_dinv[u3];
        float2 f0 = F2[u0 * 32 + lane];
        float2 f1 = F2[u1 * 32 + lane];
        float2 f2 = F2[u2 * 32 + lane];
        float2 f3 = F2[u3 * 32 + lane];
        ax += d0 * f0.x; ay += d0 * f0.y;
        ax += d1 * f1.x; ay += d1 * f1.y;
        ax += d2 * f2.x; ay += d2 * f2.y;
        ax += d3 * f3.x; ay += d3 * f3.y;
    }
    for (; e < end; e++) {
        int u = g_col[e];
        float d = g_dinv[u];
        float2 f = F2[u * 32 + lane];
        ax += d * f.x; ay += d * f.y;
    }
}

// kstep = 1..5 : g_F[kstep] = P g_F[kstep-1]   (globals resolved in device code)
__global__ __launch_bounds__(256) void k_prop(int kstep) {
    int gw = (blockIdx.x * blockDim.x + threadIdx.x) >> 5;
    if (gw >= N_NODES) return;
    int lane = threadIdx.x & 31;
    const float2* Fin  = (const float2*)&g_F[kstep - 1][0];
    float2*       Fout = (float2*)&g_F[kstep][0];
    float ax = 0.f, ay = 0.f;
    prop_accum(g_rowptr[gw], g_rowptr[gw + 1], lane, Fin, ax, ay);
    float dv = g_dinv[gw];
    float2 fv = Fin[gw * 32 + lane];
    fv.x -= dv * ax;
    fv.y -= dv * ay;
    Fout[gw * 32 + lane] = fv;
}

// Final step (k=6) fused with combine: f6 stays in registers.
// out[node, i*64+j] = sum_{k=0..5} theta[i][k]*f_k[node,j] + theta[i][6]*f6[node,j]
__global__ __launch_bounds__(256) void k_prop_last(float* __restrict__ out, ThetaPack tp) {
    int gw = (blockIdx.x * blockDim.x + threadIdx.x) >> 5;
    if (gw >= N_NODES) return;
    int lane = threadIdx.x & 31;
    const float2* F5 = (const float2*)&g_F[5][0];
    float ax = 0.f, ay = 0.f;
    prop_accum(g_rowptr[gw], g_rowptr[gw + 1], lane, F5, ax, ay);
    float dv = g_dinv[gw];
    float2 f6 = F5[gw * 32 + lane];
    f6.x -= dv * ax;
    f6.y -= dv * ay;

    float2 f[6];
    #pragma unroll
    for (int k = 0; k < 6; k++)
        f[k] = ((const float2*)&g_F[k][0])[gw * 32 + lane];

    float2* ob = (float2*)(out + (size_t)gw * (5 * H_FEATS)) + lane;
    #pragma unroll
    for (int i = 0; i < 5; i++) {
        float2 a;
        a.x = tp.t[i][6] * f6.x;
        a.y = tp.t[i][6] * f6.y;
        #pragma unroll
        for (int k = 0; k < 6; k++) {
            float c = tp.t[i][k];
            a.x += c * f[k].x;
            a.y += c * f[k].y;
        }
        ob[i * 32] = a;
    }
}

// ---------------- host: theta coefficients ----------------
static double fact_d(int n) { double r = 1.0; for (int i = 2; i <= n; i++) r *= i; return r; }

static ThetaPack make_thetas() {
    ThetaPack tp;
    const int d = 4, OFF = 2;
    const double e = 1.4;
    for (int ii = 0; ii < 5; ii++) {
        int i = OFF + ii;
        int m = d - i + OFF;
        double B = fact_d(i) * fact_d(d - i + OFF) / fact_d(d + 1 + OFF);
        double c[7] = {0, 0, 0, 0, 0, 0, 0};
        double inv_e_i = pow(1.0 / e, (double)i);
        double pj = 1.0;
        for (int j = 0; j <= m; j++) {
            double comb = fact_d(m) / (fact_d(j) * fact_d(m - j));
            c[i + j] = inv_e_i * comb * pj / (e * B);
            pj *= (-1.0 / e);
        }
        for (int k = 0; k < 7; k++) tp.t[ii][k] = (float)c[k];
    }
    return tp;
}

// ---------------- entry point ----------------
extern "C" void kernel_launch(void* const* d_in, const int* in_sizes, int n_in,
                              void* d_out, int out_size) {
    (void)in_sizes; (void)n_in; (void)out_size;
    const float* x   = (const float*)d_in[0];
    const float* W   = (const float*)d_in[1];
    const float* b   = (const float*)d_in[2];
    const int*   src = (const int*)d_in[3];
    const int*   dst = (const int*)d_in[4];
    float* out = (float*)d_out;

    ThetaPack tp = make_thetas();

    // CSR build + degrees
    k_zero<<<(N_NODES + 255) / 256, 256>>>();
    k_hist<<<(N_EDGES + 255) / 256, 256>>>(src, dst);
    k_scan_blk<<<SCAN_NBLK, 1024>>>();
    k_scan_top<<<1, 64>>>();
    k_scan_add<<<SCAN_NBLK, 1024>>>();   // rowptr finalize + d_inv
    k_scatter<<<(N_EDGES + 255) / 256, 256>>>(src, dst);

    // h = leaky_relu(xW + b) -> g_F[0]
    k_gemm<<<(N_NODES + 127) / 128, 256>>>(x, W, b);

    // f_k = P^k h, k = 1..5
    int nblk = (N_NODES + 7) / 8;
    for (int k = 1; k <= 5; k++)
        k_prop<<<nblk, 256>>>(k);

    // step 6 fused with combine (f6 never hits memory)
    k_prop_last<<<nblk, 256>>>(out, tp);
}

// round 10
// speedup vs baseline: 1.2486x; 1.0173x over previous
#include <cuda_runtime.h>
#include <math.h>

#define N_NODES  50000
#define N_EDGES  800000
#define IN_FEATS 256
#define H_FEATS  64
#define NEG_SLOPE 0.01f
#define SCAN_NBLK ((N_NODES + 1023) / 1024)   // 49

// ---------------- scratch (static __device__, no allocations) ----------------
__device__ __align__(16) float g_F[6][N_NODES * H_FEATS];  // f_k fp32, k=0..5 (76.8 MB)
__device__ int   g_cnt[N_NODES];   // zero at load (.bss) and re-zeroed by k_gemm each call
__device__ int   g_deg[N_NODES];
__device__ int   g_cur[N_NODES];
__device__ int   g_rowptr[N_NODES + 1];
__device__ int   g_col[N_EDGES];
__device__ float g_dinv[N_NODES];
__device__ int   g_bsum[64];

struct ThetaPack { float t[5][7]; };

// packed fp32x2 FMA (FFMA2) — two exact rn-FMAs per instruction
#define FFMA2(d, a, bb, c) \
    asm("fma.rn.f32x2 %0, %1, %2, %3;" : "=l"(d) : "l"(a), "l"(bb), "l"(c))
#define PACK_DUP(d, s) \
    asm("mov.b64 %0, {%1, %1};" : "=l"(d) : "r"(s))

// ---------------- CSR build ----------------
__global__ void k_hist(const int* __restrict__ src, const int* __restrict__ dst) {
    int i = blockIdx.x * blockDim.x + threadIdx.x;
    if (i < N_EDGES) {
        atomicAdd(&g_cnt[dst[i]], 1);
        atomicAdd(&g_deg[src[i]], 1);
    }
}

// Stage 1: per-block exclusive scan (1024 elems/block), block totals to g_bsum
__global__ __launch_bounds__(1024) void k_scan_blk() {
    __shared__ int warpsum[32];
    int i = blockIdx.x * 1024 + threadIdx.x;
    int lane = threadIdx.x & 31;
    int wid  = threadIdx.x >> 5;
    int v = (i < N_NODES) ? g_cnt[i] : 0;
    int x = v;
    #pragma unroll
    for (int o = 1; o < 32; o <<= 1) {
        int y = __shfl_up_sync(0xffffffffu, x, o);
        if (lane >= o) x += y;
    }
    if (lane == 31) warpsum[wid] = x;
    __syncthreads();
    if (wid == 0) {
        int w = warpsum[lane];
        #pragma unroll
        for (int o = 1; o < 32; o <<= 1) {
            int y = __shfl_up_sync(0xffffffffu, w, o);
            if (lane >= o) w += y;
        }
        warpsum[lane] = w;
    }
    __syncthreads();
    int prefix = (wid > 0 ? warpsum[wid - 1] : 0);
    if (i < N_NODES) g_rowptr[i] = prefix + x - v;
    if (threadIdx.x == 1023) g_bsum[blockIdx.x] = prefix + x;
}

// Stage 2 (fused top-scan): each block sums g_bsum[0..blockIdx-1] inline,
// adds it, and computes d_inv (g_deg final after k_hist).
__global__ __launch_bounds__(1024) void k_scan_add() {
    __shared__ int s_off;
    if (threadIdx.x < 32) {
        int off = 0;
        for (int j = threadIdx.x; j < blockIdx.x; j += 32) off += g_bsum[j];
        #pragma unroll
        for (int o = 16; o > 0; o >>= 1) off += __shfl_down_sync(0xffffffffu, off, o);
        if (threadIdx.x == 0) s_off = off;
    }
    __syncthreads();
    int i = blockIdx.x * 1024 + threadIdx.x;
    if (i < N_NODES) {
        g_rowptr[i] += s_off;
        int d = g_deg[i];
        g_dinv[i] = rsqrtf((float)(d < 1 ? 1 : d));
    }
    if (i == 0) g_rowptr[N_NODES] = N_EDGES;
}

__global__ void k_scatter(const int* __restrict__ src, const int* __restrict__ dst) {
    int i = blockIdx.x * blockDim.x + threadIdx.x;
    if (i < N_EDGES) {
        int d = dst[i];
        int pos = g_rowptr[d] + atomicAdd(&g_cur[d], 1);
        g_col[pos] = src[i];
    }
}

// ---------------- GEMM: h = leaky_relu(x @ W + b) -> g_F[0] ----------------
// 128 nodes x 64 feats per block, k-tile 16, 256 threads.
// Per thread: 4 node-pairs x 4 feats as f32x2 accumulators (FFMA2 inner loop).
// Also zeroes the CSR counters for the next invocation (runs after k_scatter).
__global__ __launch_bounds__(256) void k_gemm(const float* __restrict__ x,
                                              const float* __restrict__ W,
                                              const float* __restrict__ b) {
    __shared__ __align__(16) float xs[16][132];
    __shared__ __align__(16) float ws[16][64];
    int t  = threadIdx.x;
    int tx = t & 15;   // feats tx*4 .. tx*4+3
    int ty = t >> 4;   // nodes ty*8 .. ty*8+7 (4 pairs)
    int nodeBase = blockIdx.x * 128;

    // reset CSR counters for the next call (deterministic: zero at load,
    // re-zeroed here every call after k_scatter has consumed them)
    int gid = blockIdx.x * 256 + t;
    if (gid < N_NODES) { g_cnt[gid] = 0; g_deg[gid] = 0; g_cur[gid] = 0; }

    unsigned long long acc2[4][4];   // [node-pair][feat] = (node2ip, node2ip+1)
    #pragma unroll
    for (int i = 0; i < 4; i++)
        #pragma unroll
        for (int j = 0; j < 4; j++) acc2[i][j] = 0ull;

    for (int k0 = 0; k0 < IN_FEATS; k0 += 16) {
        #pragma unroll
        for (int r = 0; r < 2; r++) {
            int idx = t + r * 256;
            int row = idx >> 2;
            int kq  = idx & 3;
            int node = nodeBase + row;
            float4 v = make_float4(0.f, 0.f, 0.f, 0.f);
            if (node < N_NODES)
                v = *(const float4*)(x + (size_t)node * IN_FEATS + k0 + kq * 4);
            xs[kq * 4 + 0][row] = v.x;
            xs[kq * 4 + 1][row] = v.y;
            xs[kq * 4 + 2][row] = v.z;
            xs[kq * 4 + 3][row] = v.w;
        }
        {
            int kk = t >> 4;
            int fq = t & 15;
            *(float4*)&ws[kk][fq * 4] = *(const float4*)(W + (size_t)(k0 + kk) * H_FEATS + fq * 4);
        }
        __syncthreads();
        #pragma unroll
        for (int k = 0; k < 16; k++) {
            float4 wv = *(const float4*)&ws[k][tx * 4];
            // node pairs directly as packed 64-bit lanes (consecutive nodes in xs)
            ulonglong2 xpA = *(const ulonglong2*)&xs[k][ty * 8];      // pairs (n0n1),(n2n3)
            ulonglong2 xpB = *(const ulonglong2*)&xs[k][ty * 8 + 4];  // pairs (n4n5),(n6n7)
            unsigned long long wp0, wp1, wp2, wp3;
            PACK_DUP(wp0, __float_as_uint(wv.x));
            PACK_DUP(wp1, __float_as_uint(wv.y));
            PACK_DUP(wp2, __float_as_uint(wv.z));
            PACK_DUP(wp3, __float_as_uint(wv.w));
            FFMA2(acc2[0][0], xpA.x, wp0, acc2[0][0]);
            FFMA2(acc2[0][1], xpA.x, wp1, acc2[0][1]);
            FFMA2(acc2[0][2], xpA.x, wp2, acc2[0][2]);
            FFMA2(acc2[0][3], xpA.x, wp3, acc2[0][3]);
            FFMA2(acc2[1][0], xpA.y, wp0, acc2[1][0]);
            FFMA2(acc2[1][1], xpA.y, wp1, acc2[1][1]);
            FFMA2(acc2[1][2], xpA.y, wp2, acc2[1][2]);
            FFMA2(acc2[1][3], xpA.y, wp3, acc2[1][3]);
            FFMA2(acc2[2][0], xpB.x, wp0, acc2[2][0]);
            FFMA2(acc2[2][1], xpB.x, wp1, acc2[2][1]);
            FFMA2(acc2[2][2], xpB.x, wp2, acc2[2][2]);
            FFMA2(acc2[2][3], xpB.x, wp3, acc2[2][3]);
            FFMA2(acc2[3][0], xpB.y, wp0, acc2[3][0]);
            FFMA2(acc2[3][1], xpB.y, wp1, acc2[3][1]);
            FFMA2(acc2[3][2], xpB.y, wp2, acc2[3][2]);
            FFMA2(acc2[3][3], xpB.y, wp3, acc2[3][3]);
        }
        __syncthreads();
    }
    float4 bv = *(const float4*)(b + tx * 4);
    #pragma unroll
    for (int ip = 0; ip < 4; ip++) {
        float2 a0 = *(float2*)&acc2[ip][0];
        float2 a1 = *(float2*)&acc2[ip][1];
        float2 a2 = *(float2*)&acc2[ip][2];
        float2 a3 = *(float2*)&acc2[ip][3];
        int nodeA = nodeBase + ty * 8 + 2 * ip;
        if (nodeA < N_NODES) {
            float4 o;
            o.x = a0.x + bv.x; o.y = a1.x + bv.y;
            o.z = a2.x + bv.z; o.w = a3.x + bv.w;
            o.x = o.x >= 0.f ? o.x : NEG_SLOPE * o.x;
            o.y = o.y >= 0.f ? o.y : NEG_SLOPE * o.y;
            o.z = o.z >= 0.f ? o.z : NEG_SLOPE * o.z;
            o.w = o.w >= 0.f ? o.w : NEG_SLOPE * o.w;
            *(float4*)&g_F[0][(size_t)nodeA * H_FEATS + tx * 4] = o;
        }
        int nodeB = nodeA + 1;
        if (nodeB < N_NODES) {
            float4 o;
            o.x = a0.y + bv.x; o.y = a1.y + bv.y;
            o.z = a2.y + bv.z; o.w = a3.y + bv.w;
            o.x = o.x >= 0.f ? o.x : NEG_SLOPE * o.x;
            o.y = o.y >= 0.f ? o.y : NEG_SLOPE * o.y;
            o.z = o.z >= 0.f ? o.z : NEG_SLOPE * o.z;
            o.w = o.w >= 0.f ? o.w : NEG_SLOPE * o.w;
            *(float4*)&g_F[0][(size_t)nodeB * H_FEATS + tx * 4] = o;
        }
    }
}

// ---------------- propagation (fp32 gather, warp per node) ----------------
__device__ __forceinline__ void prop_accum(int beg, int end, int lane,
                                           const float2* __restrict__ F2,
                                           float& ax, float& ay) {
    int e = beg;
    for (; e + 4 <= end; e += 4) {
        int u0 = g_col[e + 0];
        int u1 = g_col[e + 1];
        int u2 = g_col[e + 2];
        int u3 = g_col[e + 3];
        float d0 = g_dinv[u0], d1 = g_dinv[u1], d2 = g_dinv[u2], d3 = g_dinv[u3];
        float2 f0 = F2[u0 * 32 + lane];
        float2 f1 = F2[u1 * 32 + lane];
        float2 f2 = F2[u2 * 32 + lane];
        float2 f3 = F2[u3 * 32 + lane];
        ax += d0 * f0.x; ay += d0 * f0.y;
        ax += d1 * f1.x; ay += d1 * f1.y;
        ax += d2 * f2.x; ay += d2 * f2.y;
        ax += d3 * f3.x; ay += d3 * f3.y;
    }
    for (; e < end; e++) {
        int u = g_col[e];
        float d = g_dinv[u];
        float2 f = F2[u * 32 + lane];
        ax += d * f.x; ay += d * f.y;
    }
}

// kstep = 1..5 : g_F[kstep] = P g_F[kstep-1]   (globals resolved in device code)
__global__ __launch_bounds__(256) void k_prop(int kstep) {
    int gw = (blockIdx.x * blockDim.x + threadIdx.x) >> 5;
    if (gw >= N_NODES) return;
    int lane = threadIdx.x & 31;
    const float2* Fin  = (const float2*)&g_F[kstep - 1][0];
    float2*       Fout = (float2*)&g_F[kstep][0];
    float ax = 0.f, ay = 0.f;
    prop_accum(g_rowptr[gw], g_rowptr[gw + 1], lane, Fin, ax, ay);
    float dv = g_dinv[gw];
    float2 fv = Fin[gw * 32 + lane];
    fv.x -= dv * ax;
    fv.y -= dv * ay;
    Fout[gw * 32 + lane] = fv;
}

// Final step (k=6) fused with combine: f6 stays in registers.
__global__ __launch_bounds__(256) void k_prop_last(float* __restrict__ out, ThetaPack tp) {
    int gw = (blockIdx.x * blockDim.x + threadIdx.x) >> 5;
    if (gw >= N_NODES) return;
    int lane = threadIdx.x & 31;
    const float2* F5 = (const float2*)&g_F[5][0];
    float ax = 0.f, ay = 0.f;
    prop_accum(g_rowptr[gw], g_rowptr[gw + 1], lane, F5, ax, ay);
    float dv = g_dinv[gw];
    float2 f6 = F5[gw * 32 + lane];
    f6.x -= dv * ax;
    f6.y -= dv * ay;

    float2 f[6];
    #pragma unroll
    for (int k = 0; k < 6; k++)
        f[k] = ((const float2*)&g_F[k][0])[gw * 32 + lane];

    float2* ob = (float2*)(out + (size_t)gw * (5 * H_FEATS)) + lane;
    #pragma unroll
    for (int i = 0; i < 5; i++) {
        float2 a;
        a.x = tp.t[i][6] * f6.x;
        a.y = tp.t[i][6] * f6.y;
        #pragma unroll
        for (int k = 0; k < 6; k++) {
            float c = tp.t[i][k];
            a.x += c * f[k].x;
            a.y += c * f[k].y;
        }
        ob[i * 32] = a;
    }
}

// ---------------- host: theta coefficients ----------------
static double fact_d(int n) { double r = 1.0; for (int i = 2; i <= n; i++) r *= i; return r; }

static ThetaPack make_thetas() {
    ThetaPack tp;
    const int d = 4, OFF = 2;
    const double e = 1.4;
    for (int ii = 0; ii < 5; ii++) {
        int i = OFF + ii;
        int m = d - i + OFF;
        double B = fact_d(i) * fact_d(d - i + OFF) / fact_d(d + 1 + OFF);
        double c[7] = {0, 0, 0, 0, 0, 0, 0};
        double inv_e_i = pow(1.0 / e, (double)i);
        double pj = 1.0;
        for (int j = 0; j <= m; j++) {
            double comb = fact_d(m) / (fact_d(j) * fact_d(m - j));
            c[i + j] = inv_e_i * comb * pj / (e * B);
            pj *= (-1.0 / e);
        }
        for (int k = 0; k < 7; k++) tp.t[ii][k] = (float)c[k];
    }
    return tp;
}

// ---------------- entry point ----------------
extern "C" void kernel_launch(void* const* d_in, const int* in_sizes, int n_in,
                              void* d_out, int out_size) {
    (void)in_sizes; (void)n_in; (void)out_size;
    const float* x   = (const float*)d_in[0];
    const float* W   = (const float*)d_in[1];
    const float* b   = (const float*)d_in[2];
    const int*   src = (const int*)d_in[3];
    const int*   dst = (const int*)d_in[4];
    float* out = (float*)d_out;

    ThetaPack tp = make_thetas();

    // CSR build (counters arrive zeroed: .bss at load, re-zeroed by k_gemm each call)
    k_hist<<<(N_EDGES + 255) / 256, 256>>>(src, dst);
    k_scan_blk<<<SCAN_NBLK, 1024>>>();
    k_scan_add<<<SCAN_NBLK, 1024>>>();   // top-scan fused + rowptr finalize + d_inv
    k_scatter<<<(N_EDGES + 255) / 256, 256>>>(src, dst);

    // h = leaky_relu(xW + b) -> g_F[0]  (FFMA2 inner loop; also re-zeroes counters)
    k_gemm<<<(N_NODES + 127) / 128, 256>>>(x, W, b);

    // f_k = P^k h, k = 1..5
    int nblk = (N_NODES + 7) / 8;
    for (int k = 1; k <= 5; k++)
        k_prop<<<nblk, 256>>>(k);

    // step 6 fused with combine (f6 never hits memory)
    k_prop_last<<<nblk, 256>>>(out, tp);
}

// round 11
// speedup vs baseline: 1.2602x; 1.0093x over previous
#include <cuda_runtime.h>
#include <math.h>

#define N_NODES  50000
#define N_EDGES  800000
#define IN_FEATS 256
#define H_FEATS  64
#define NEG_SLOPE 0.01f
#define SCAN_NBLK ((N_NODES + 1023) / 1024)   // 49

// ---------------- scratch (static __device__, no allocations) ----------------
__device__ __align__(16) float g_F[6][N_NODES * H_FEATS];  // f_k fp32, k=0..5 (76.8 MB)
__device__ int   g_cnt[N_NODES];   // zero at load (.bss), re-zeroed by k_gemm each call
__device__ int   g_deg[N_NODES];
__device__ int   g_rowptr[N_NODES + 1];
__device__ __align__(16) int g_rank[N_EDGES]; // edge rank within its dst row (from hist atomic)
__device__ int   g_col[N_EDGES];
__device__ float g_dinv[N_NODES];
__device__ int   g_bsum[64];

struct ThetaPack { float t[5][7]; };

// packed fp32x2 FMA (FFMA2) — two exact rn-FMAs per instruction
#define FFMA2(d, a, bb, c) \
    asm("fma.rn.f32x2 %0, %1, %2, %3;" : "=l"(d) : "l"(a), "l"(bb), "l"(c))
#define PACK_DUP(d, s) \
    asm("mov.b64 %0, {%1, %1};" : "=l"(d) : "r"(s))

// ---------------- CSR build ----------------
// hist + rank capture: the atomic's return value IS the edge's rank in its row.
__global__ void k_hist(const int* __restrict__ src, const int* __restrict__ dst) {
    int i = blockIdx.x * blockDim.x + threadIdx.x;
    if (i < N_EDGES) {
        g_rank[i] = atomicAdd(&g_cnt[dst[i]], 1);
        atomicAdd(&g_deg[src[i]], 1);
    }
}

// Stage 1: per-block exclusive scan (1024 elems/block), block totals to g_bsum
__global__ __launch_bounds__(1024) void k_scan_blk() {
    __shared__ int warpsum[32];
    int i = blockIdx.x * 1024 + threadIdx.x;
    int lane = threadIdx.x & 31;
    int wid  = threadIdx.x >> 5;
    int v = (i < N_NODES) ? g_cnt[i] : 0;
    int x = v;
    #pragma unroll
    for (int o = 1; o < 32; o <<= 1) {
        int y = __shfl_up_sync(0xffffffffu, x, o);
        if (lane >= o) x += y;
    }
    if (lane == 31) warpsum[wid] = x;
    __syncthreads();
    if (wid == 0) {
        int w = warpsum[lane];
        #pragma unroll
        for (int o = 1; o < 32; o <<= 1) {
            int y = __shfl_up_sync(0xffffffffu, w, o);
            if (lane >= o) w += y;
        }
        warpsum[lane] = w;
    }
    __syncthreads();
    int prefix = (wid > 0 ? warpsum[wid - 1] : 0);
    if (i < N_NODES) g_rowptr[i] = prefix + x - v;
    if (threadIdx.x == 1023) g_bsum[blockIdx.x] = prefix + x;
}

// Stage 2 (fused top-scan): each block sums g_bsum[0..blockIdx-1] inline,
// adds it, and computes d_inv (g_deg final after k_hist).
__global__ __launch_bounds__(1024) void k_scan_add() {
    __shared__ int s_off;
    if (threadIdx.x < 32) {
        int off = 0;
        for (int j = threadIdx.x; j < blockIdx.x; j += 32) off += g_bsum[j];
        #pragma unroll
        for (int o = 16; o > 0; o >>= 1) off += __shfl_down_sync(0xffffffffu, off, o);
        if (threadIdx.x == 0) s_off = off;
    }
    __syncthreads();
    int i = blockIdx.x * 1024 + threadIdx.x;
    if (i < N_NODES) {
        g_rowptr[i] += s_off;
        int d = g_deg[i];
        g_dinv[i] = rsqrtf((float)(d < 1 ? 1 : d));
    }
    if (i == 0) g_rowptr[N_NODES] = N_EDGES;
}

// Atomic-free scatter: position = rowptr[dst] + rank. 4 edges/thread, int4 loads.
__global__ __launch_bounds__(256) void k_scatter(const int* __restrict__ src,
                                                 const int* __restrict__ dst) {
    int q = blockIdx.x * blockDim.x + threadIdx.x;   // quad index
    if (q >= N_EDGES / 4) return;
    int4 d4 = ((const int4*)dst)[q];
    int4 r4 = ((const int4*)g_rank)[q];
    int4 s4 = ((const int4*)src)[q];
    g_col[g_rowptr[d4.x] + r4.x] = s4.x;
    g_col[g_rowptr[d4.y] + r4.y] = s4.y;
    g_col[g_rowptr[d4.z] + r4.z] = s4.z;
    g_col[g_rowptr[d4.w] + r4.w] = s4.w;
}

// ---------------- GEMM: h = leaky_relu(x @ W + b) -> g_F[0] ----------------
// 128 nodes x 64 feats per block, k-tile 16, 256 threads, FFMA2 inner loop.
// Also zeroes the CSR counters for the next invocation (runs after k_scatter).
__global__ __launch_bounds__(256) void k_gemm(const float* __restrict__ x,
                                              const float* __restrict__ W,
                                              const float* __restrict__ b) {
    __shared__ __align__(16) float xs[16][132];
    __shared__ __align__(16) float ws[16][64];
    int t  = threadIdx.x;
    int tx = t & 15;   // feats tx*4 .. tx*4+3
    int ty = t >> 4;   // nodes ty*8 .. ty*8+7 (4 pairs)
    int nodeBase = blockIdx.x * 128;

    // reset CSR counters for the next call
    int gid = blockIdx.x * 256 + t;
    if (gid < N_NODES) { g_cnt[gid] = 0; g_deg[gid] = 0; }

    unsigned long long acc2[4][4];
    #pragma unroll
    for (int i = 0; i < 4; i++)
        #pragma unroll
        for (int j = 0; j < 4; j++) acc2[i][j] = 0ull;

    for (int k0 = 0; k0 < IN_FEATS; k0 += 16) {
        #pragma unroll
        for (int r = 0; r < 2; r++) {
            int idx = t + r * 256;
            int row = idx >> 2;
            int kq  = idx & 3;
            int node = nodeBase + row;
            float4 v = make_float4(0.f, 0.f, 0.f, 0.f);
            if (node < N_NODES)
                v = *(const float4*)(x + (size_t)node * IN_FEATS + k0 + kq * 4);
            xs[kq * 4 + 0][row] = v.x;
            xs[kq * 4 + 1][row] = v.y;
            xs[kq * 4 + 2][row] = v.z;
            xs[kq * 4 + 3][row] = v.w;
        }
        {
            int kk = t >> 4;
            int fq = t & 15;
            *(float4*)&ws[kk][fq * 4] = *(const float4*)(W + (size_t)(k0 + kk) * H_FEATS + fq * 4);
        }
        __syncthreads();
        #pragma unroll
        for (int k = 0; k < 16; k++) {
            float4 wv = *(const float4*)&ws[k][tx * 4];
            ulonglong2 xpA = *(const ulonglong2*)&xs[k][ty * 8];
            ulonglong2 xpB = *(const ulonglong2*)&xs[k][ty * 8 + 4];
            unsigned long long wp0, wp1, wp2, wp3;
            PACK_DUP(wp0, __float_as_uint(wv.x));
            PACK_DUP(wp1, __float_as_uint(wv.y));
            PACK_DUP(wp2, __float_as_uint(wv.z));
            PACK_DUP(wp3, __float_as_uint(wv.w));
            FFMA2(acc2[0][0], xpA.x, wp0, acc2[0][0]);
            FFMA2(acc2[0][1], xpA.x, wp1, acc2[0][1]);
            FFMA2(acc2[0][2], xpA.x, wp2, acc2[0][2]);
            FFMA2(acc2[0][3], xpA.x, wp3, acc2[0][3]);
            FFMA2(acc2[1][0], xpA.y, wp0, acc2[1][0]);
            FFMA2(acc2[1][1], xpA.y, wp1, acc2[1][1]);
            FFMA2(acc2[1][2], xpA.y, wp2, acc2[1][2]);
            FFMA2(acc2[1][3], xpA.y, wp3, acc2[1][3]);
            FFMA2(acc2[2][0], xpB.x, wp0, acc2[2][0]);
            FFMA2(acc2[2][1], xpB.x, wp1, acc2[2][1]);
            FFMA2(acc2[2][2], xpB.x, wp2, acc2[2][2]);
            FFMA2(acc2[2][3], xpB.x, wp3, acc2[2][3]);
            FFMA2(acc2[3][0], xpB.y, wp0, acc2[3][0]);
            FFMA2(acc2[3][1], xpB.y, wp1, acc2[3][1]);
            FFMA2(acc2[3][2], xpB.y, wp2, acc2[3][2]);
            FFMA2(acc2[3][3], xpB.y, wp3, acc2[3][3]);
        }
        __syncthreads();
    }
    float4 bv = *(const float4*)(b + tx * 4);
    #pragma unroll
    for (int ip = 0; ip < 4; ip++) {
        float2 a0 = *(float2*)&acc2[ip][0];
        float2 a1 = *(float2*)&acc2[ip][1];
        float2 a2 = *(float2*)&acc2[ip][2];
        float2 a3 = *(float2*)&acc2[ip][3];
        int nodeA = nodeBase + ty * 8 + 2 * ip;
        if (nodeA < N_NODES) {
            float4 o;
            o.x = a0.x + bv.x; o.y = a1.x + bv.y;
            o.z = a2.x + bv.z; o.w = a3.x + bv.w;
            o.x = o.x >= 0.f ? o.x : NEG_SLOPE * o.x;
            o.y = o.y >= 0.f ? o.y : NEG_SLOPE * o.y;
            o.z = o.z >= 0.f ? o.z : NEG_SLOPE * o.z;
            o.w = o.w >= 0.f ? o.w : NEG_SLOPE * o.w;
            *(float4*)&g_F[0][(size_t)nodeA * H_FEATS + tx * 4] = o;
        }
        int nodeB = nodeA + 1;
        if (nodeB < N_NODES) {
            float4 o;
            o.x = a0.y + bv.x; o.y = a1.y + bv.y;
            o.z = a2.y + bv.z; o.w = a3.y + bv.w;
            o.x = o.x >= 0.f ? o.x : NEG_SLOPE * o.x;
            o.y = o.y >= 0.f ? o.y : NEG_SLOPE * o.y;
            o.z = o.z >= 0.f ? o.z : NEG_SLOPE * o.z;
            o.w = o.w >= 0.f ? o.w : NEG_SLOPE * o.w;
            *(float4*)&g_F[0][(size_t)nodeB * H_FEATS + tx * 4] = o;
        }
    }
}

// ---------------- propagation (fp32 gather, warp per node) ----------------
__device__ __forceinline__ void prop_accum(int beg, int end, int lane,
                                           const float2* __restrict__ F2,
                                           float& ax, float& ay) {
    int e = beg;
    for (; e + 4 <= end; e += 4) {
        int u0 = g_col[e + 0];
        int u1 = g_col[e + 1];
        int u2 = g_col[e + 2];
        int u3 = g_col[e + 3];
        float d0 = g_dinv[u0], d1 = g_dinv[u1], d2 = g_dinv[u2], d3 = g_dinv[u3];
        float2 f0 = F2[u0 * 32 + lane];
        float2 f1 = F2[u1 * 32 + lane];
        float2 f2 = F2[u2 * 32 + lane];
        float2 f3 = F2[u3 * 32 + lane];
        ax += d0 * f0.x; ay += d0 * f0.y;
        ax += d1 * f1.x; ay += d1 * f1.y;
        ax += d2 * f2.x; ay += d2 * f2.y;
        ax += d3 * f3.x; ay += d3 * f3.y;
    }
    for (; e < end; e++) {
        int u = g_col[e];
        float d = g_dinv[u];
        float2 f = F2[u * 32 + lane];
        ax += d * f.x; ay += d * f.y;
    }
}

// kstep = 1..5 : g_F[kstep] = P g_F[kstep-1]   (globals resolved in device code)
__global__ __launch_bounds__(256) void k_prop(int kstep) {
    int gw = (blockIdx.x * blockDim.x + threadIdx.x) >> 5;
    if (gw >= N_NODES) return;
    int lane = threadIdx.x & 31;
    const float2* Fin  = (const float2*)&g_F[kstep - 1][0];
    float2*       Fout = (float2*)&g_F[kstep][0];
    float ax = 0.f, ay = 0.f;
    prop_accum(g_rowptr[gw], g_rowptr[gw + 1], lane, Fin, ax, ay);
    float dv = g_dinv[gw];
    float2 fv = Fin[gw * 32 + lane];
    fv.x -= dv * ax;
    fv.y -= dv * ay;
    Fout[gw * 32 + lane] = fv;
}

// Final step (k=6) fused with combine: f6 stays in registers.
__global__ __launch_bounds__(256) void k_prop_last(float* __restrict__ out, ThetaPack tp) {
    int gw = (blockIdx.x * blockDim.x + threadIdx.x) >> 5;
    if (gw >= N_NODES) return;
    int lane = threadIdx.x & 31;
    const float2* F5 = (const float2*)&g_F[5][0];
    float ax = 0.f, ay = 0.f;
    prop_accum(g_rowptr[gw], g_rowptr[gw + 1], lane, F5, ax, ay);
    float dv = g_dinv[gw];
    float2 f6 = F5[gw * 32 + lane];
    f6.x -= dv * ax;
    f6.y -= dv * ay;

    float2 f[6];
    #pragma unroll
    for (int k = 0; k < 6; k++)
        f[k] = ((const float2*)&g_F[k][0])[gw * 32 + lane];

    float2* ob = (float2*)(out + (size_t)gw * (5 * H_FEATS)) + lane;
    #pragma unroll
    for (int i = 0; i < 5; i++) {
        float2 a;
        a.x = tp.t[i][6] * f6.x;
        a.y = tp.t[i][6] * f6.y;
        #pragma unroll
        for (int k = 0; k < 6; k++) {
            float c = tp.t[i][k];
            a.x += c * f[k].x;
            a.y += c * f[k].y;
        }
        ob[i * 32] = a;
    }
}

// ---------------- host: theta coefficients ----------------
static double fact_d(int n) { double r = 1.0; for (int i = 2; i <= n; i++) r *= i; return r; }

static ThetaPack make_thetas() {
    ThetaPack tp;
    const int d = 4, OFF = 2;
    const double e = 1.4;
    for (int ii = 0; ii < 5; ii++) {
        int i = OFF + ii;
        int m = d - i + OFF;
        double B = fact_d(i) * fact_d(d - i + OFF) / fact_d(d + 1 + OFF);
        double c[7] = {0, 0, 0, 0, 0, 0, 0};
        double inv_e_i = pow(1.0 / e, (double)i);
        double pj = 1.0;
        for (int j = 0; j <= m; j++) {
            double comb = fact_d(m) / (fact_d(j) * fact_d(m - j));
            c[i + j] = inv_e_i * comb * pj / (e * B);
            pj *= (-1.0 / e);
        }
        for (int k = 0; k < 7; k++) tp.t[ii][k] = (float)c[k];
    }
    return tp;
}

// ---------------- entry point ----------------
extern "C" void kernel_launch(void* const* d_in, const int* in_sizes, int n_in,
                              void* d_out, int out_size) {
    (void)in_sizes; (void)n_in; (void)out_size;
    const float* x   = (const float*)d_in[0];
    const float* W   = (const float*)d_in[1];
    const float* b   = (const float*)d_in[2];
    const int*   src = (const int*)d_in[3];
    const int*   dst = (const int*)d_in[4];
    float* out = (float*)d_out;

    ThetaPack tp = make_thetas();

    // CSR build (counters arrive zeroed: .bss at load, re-zeroed by k_gemm each call)
    k_hist<<<(N_EDGES + 255) / 256, 256>>>(src, dst);   // also captures per-edge rank
    k_scan_blk<<<SCAN_NBLK, 1024>>>();
    k_scan_add<<<SCAN_NBLK, 1024>>>();                  // top-scan fused + d_inv
    k_scatter<<<(N_EDGES / 4 + 255) / 256, 256>>>(src, dst);  // atomic-free

    // h = leaky_relu(xW + b) -> g_F[0]  (FFMA2; also re-zeroes counters)
    k_gemm<<<(N_NODES + 127) / 128, 256>>>(x, W, b);

    // f_k = P^k h, k = 1..5
    int nblk = (N_NODES + 7) / 8;
    for (int k = 1; k <= 5; k++)
        k_prop<<<nblk, 256>>>(k);

    // step 6 fused with combine (f6 never hits memory)
    k_prop_last<<<nblk, 256>>>(out, tp);
}

// round 12
// speedup vs baseline: 1.4168x; 1.1243x over previous
#include <cuda_runtime.h>
#include <math.h>

#define N_NODES  50000
#define N_EDGES  800000
#define IN_FEATS 256
#define H_FEATS  64
#define NEG_SLOPE 0.01f
#define SCAN_NBLK ((N_NODES + 1023) / 1024)   // 49

// ---------------- scratch (static __device__, no allocations) ----------------
__device__ __align__(16) float g_F[6][N_NODES * H_FEATS];  // f_k fp32, k=0..5 (76.8 MB)
__device__ int   g_cnt[N_NODES];   // zero at load (.bss), re-zeroed by k_scatter each call
__device__ int   g_deg[N_NODES];
__device__ int   g_rowptr[N_NODES + 1];
__device__ __align__(16) int g_rank[N_EDGES]; // edge rank within its dst row (from hist atomic)
__device__ int   g_col[N_EDGES];
__device__ float g_dinv[N_NODES];
__device__ int   g_bsum[64];

struct ThetaPack { float t[5][7]; };

// packed fp32x2 FMA (FFMA2) — two exact rn-FMAs per instruction
#define FFMA2(d, a, bb, c) \
    asm("fma.rn.f32x2 %0, %1, %2, %3;" : "=l"(d) : "l"(a), "l"(bb), "l"(c))
#define PACK_DUP(d, s) \
    asm("mov.b64 %0, {%1, %1};" : "=l"(d) : "r"(s))

// ---------------- CSR build ----------------
// hist + rank capture: the atomic's return value IS the edge's rank in its row.
__global__ void k_hist(const int* __restrict__ src, const int* __restrict__ dst) {
    int i = blockIdx.x * blockDim.x + threadIdx.x;
    if (i < N_EDGES) {
        g_rank[i] = atomicAdd(&g_cnt[dst[i]], 1);
        atomicAdd(&g_deg[src[i]], 1);
    }
}

// Stage 1: per-block exclusive scan (1024 elems/block), block totals to g_bsum
__global__ __launch_bounds__(1024) void k_scan_blk() {
    __shared__ int warpsum[32];
    int i = blockIdx.x * 1024 + threadIdx.x;
    int lane = threadIdx.x & 31;
    int wid  = threadIdx.x >> 5;
    int v = (i < N_NODES) ? g_cnt[i] : 0;
    int x = v;
    #pragma unroll
    for (int o = 1; o < 32; o <<= 1) {
        int y = __shfl_up_sync(0xffffffffu, x, o);
        if (lane >= o) x += y;
    }
    if (lane == 31) warpsum[wid] = x;
    __syncthreads();
    if (wid == 0) {
        int w = warpsum[lane];
        #pragma unroll
        for (int o = 1; o < 32; o <<= 1) {
            int y = __shfl_up_sync(0xffffffffu, w, o);
            if (lane >= o) w += y;
        }
        warpsum[lane] = w;
    }
    __syncthreads();
    int prefix = (wid > 0 ? warpsum[wid - 1] : 0);
    if (i < N_NODES) g_rowptr[i] = prefix + x - v;
    if (threadIdx.x == 1023) g_bsum[blockIdx.x] = prefix + x;
}

// Stage 2 (fused top-scan): each block sums g_bsum[0..blockIdx-1] inline,
// adds it, and computes d_inv (g_deg final after k_hist).
__global__ __launch_bounds__(1024) void k_scan_add() {
    __shared__ int s_off;
    if (threadIdx.x < 32) {
        int off = 0;
        for (int j = threadIdx.x; j < blockIdx.x; j += 32) off += g_bsum[j];
        #pragma unroll
        for (int o = 16; o > 0; o >>= 1) off += __shfl_down_sync(0xffffffffu, off, o);
        if (threadIdx.x == 0) s_off = off;
    }
    __syncthreads();
    int i = blockIdx.x * 1024 + threadIdx.x;
    if (i < N_NODES) {
        g_rowptr[i] += s_off;
        int d = g_deg[i];
        g_dinv[i] = rsqrtf((float)(d < 1 ? 1 : d));
    }
    if (i == 0) g_rowptr[N_NODES] = N_EDGES;
}

// Atomic-free scatter: position = rowptr[dst] + rank. 4 edges/thread, int4 loads.
// Also re-zeroes CSR counters for the next call (runs after their last readers).
__global__ __launch_bounds__(256) void k_scatter(const int* __restrict__ src,
                                                 const int* __restrict__ dst) {
    int q = blockIdx.x * blockDim.x + threadIdx.x;   // quad index
    if (q < N_NODES) { g_cnt[q] = 0; g_deg[q] = 0; }
    if (q >= N_EDGES / 4) return;
    int4 d4 = ((const int4*)dst)[q];
    int4 r4 = ((const int4*)g_rank)[q];
    int4 s4 = ((const int4*)src)[q];
    g_col[g_rowptr[d4.x] + r4.x] = s4.x;
    g_col[g_rowptr[d4.y] + r4.y] = s4.y;
    g_col[g_rowptr[d4.z] + r4.z] = s4.z;
    g_col[g_rowptr[d4.w] + r4.w] = s4.w;
}

// ---------------- GEMM: h = leaky_relu(x @ W + b) -> g_F[0] ----------------
// 128 nodes x 64 feats per block, k-tile 16, 256 threads, FFMA2 inner loop.
// Fully independent of the CSR chain: runs on a forked stream.
__global__ __launch_bounds__(256) void k_gemm(const float* __restrict__ x,
                                              const float* __restrict__ W,
                                              const float* __restrict__ b) {
    __shared__ __align__(16) float xs[16][132];
    __shared__ __align__(16) float ws[16][64];
    int t  = threadIdx.x;
    int tx = t & 15;   // feats tx*4 .. tx*4+3
    int ty = t >> 4;   // nodes ty*8 .. ty*8+7 (4 pairs)
    int nodeBase = blockIdx.x * 128;

    unsigned long long acc2[4][4];
    #pragma unroll
    for (int i = 0; i < 4; i++)
        #pragma unroll
        for (int j = 0; j < 4; j++) acc2[i][j] = 0ull;

    for (int k0 = 0; k0 < IN_FEATS; k0 += 16) {
        #pragma unroll
        for (int r = 0; r < 2; r++) {
            int idx = t + r * 256;
            int row = idx >> 2;
            int kq  = idx & 3;
            int node = nodeBase + row;
            float4 v = make_float4(0.f, 0.f, 0.f, 0.f);
            if (node < N_NODES)
                v = *(const float4*)(x + (size_t)node * IN_FEATS + k0 + kq * 4);
            xs[kq * 4 + 0][row] = v.x;
            xs[kq * 4 + 1][row] = v.y;
            xs[kq * 4 + 2][row] = v.z;
            xs[kq * 4 + 3][row] = v.w;
        }
        {
            int kk = t >> 4;
            int fq = t & 15;
            *(float4*)&ws[kk][fq * 4] = *(const float4*)(W + (size_t)(k0 + kk) * H_FEATS + fq * 4);
        }
        __syncthreads();
        #pragma unroll
        for (int k = 0; k < 16; k++) {
            float4 wv = *(const float4*)&ws[k][tx * 4];
            ulonglong2 xpA = *(const ulonglong2*)&xs[k][ty * 8];
            ulonglong2 xpB = *(const ulonglong2*)&xs[k][ty * 8 + 4];
            unsigned long long wp0, wp1, wp2, wp3;
            PACK_DUP(wp0, __float_as_uint(wv.x));
            PACK_DUP(wp1, __float_as_uint(wv.y));
            PACK_DUP(wp2, __float_as_uint(wv.z));
            PACK_DUP(wp3, __float_as_uint(wv.w));
            FFMA2(acc2[0][0], xpA.x, wp0, acc2[0][0]);
            FFMA2(acc2[0][1], xpA.x, wp1, acc2[0][1]);
            FFMA2(acc2[0][2], xpA.x, wp2, acc2[0][2]);
            FFMA2(acc2[0][3], xpA.x, wp3, acc2[0][3]);
            FFMA2(acc2[1][0], xpA.y, wp0, acc2[1][0]);
            FFMA2(acc2[1][1], xpA.y, wp1, acc2[1][1]);
            FFMA2(acc2[1][2], xpA.y, wp2, acc2[1][2]);
            FFMA2(acc2[1][3], xpA.y, wp3, acc2[1][3]);
            FFMA2(acc2[2][0], xpB.x, wp0, acc2[2][0]);
            FFMA2(acc2[2][1], xpB.x, wp1, acc2[2][1]);
            FFMA2(acc2[2][2], xpB.x, wp2, acc2[2][2]);
            FFMA2(acc2[2][3], xpB.x, wp3, acc2[2][3]);
            FFMA2(acc2[3][0], xpB.y, wp0, acc2[3][0]);
            FFMA2(acc2[3][1], xpB.y, wp1, acc2[3][1]);
            FFMA2(acc2[3][2], xpB.y, wp2, acc2[3][2]);
            FFMA2(acc2[3][3], xpB.y, wp3, acc2[3][3]);
        }
        __syncthreads();
    }
    float4 bv = *(const float4*)(b + tx * 4);
    #pragma unroll
    for (int ip = 0; ip < 4; ip++) {
        float2 a0 = *(float2*)&acc2[ip][0];
        float2 a1 = *(float2*)&acc2[ip][1];
        float2 a2 = *(float2*)&acc2[ip][2];
        float2 a3 = *(float2*)&acc2[ip][3];
        int nodeA = nodeBase + ty * 8 + 2 * ip;
        if (nodeA < N_NODES) {
            float4 o;
            o.x = a0.x + bv.x; o.y = a1.x + bv.y;
            o.z = a2.x + bv.z; o.w = a3.x + bv.w;
            o.x = o.x >= 0.f ? o.x : NEG_SLOPE * o.x;
            o.y = o.y >= 0.f ? o.y : NEG_SLOPE * o.y;
            o.z = o.z >= 0.f ? o.z : NEG_SLOPE * o.z;
            o.w = o.w >= 0.f ? o.w : NEG_SLOPE * o.w;
            *(float4*)&g_F[0][(size_t)nodeA * H_FEATS + tx * 4] = o;
        }
        int nodeB = nodeA + 1;
        if (nodeB < N_NODES) {
            float4 o;
            o.x = a0.y + bv.x; o.y = a1.y + bv.y;
            o.z = a2.y + bv.z; o.w = a3.y + bv.w;
            o.x = o.x >= 0.f ? o.x : NEG_SLOPE * o.x;
            o.y = o.y >= 0.f ? o.y : NEG_SLOPE * o.y;
            o.z = o.z >= 0.f ? o.z : NEG_SLOPE * o.z;
            o.w = o.w >= 0.f ? o.w : NEG_SLOPE * o.w;
            *(float4*)&g_F[0][(size_t)nodeB * H_FEATS + tx * 4] = o;
        }
    }
}

// ---------------- propagation (fp32 gather, warp per node) ----------------
__device__ __forceinline__ void prop_accum(int beg, int end, int lane,
                                           const float2* __restrict__ F2,
                                           float& ax, float& ay) {
    int e = beg;
    for (; e + 4 <= end; e += 4) {
        int u0 = g_col[e + 0];
        int u1 = g_col[e + 1];
        int u2 = g_col[e + 2];
        int u3 = g_col[e + 3];
        float d0 = g_dinv[u0], d1 = g_dinv[u1], d2 = g_dinv[u2], d3 = g_dinv[u3];
        float2 f0 = F2[u0 * 32 + lane];
        float2 f1 = F2[u1 * 32 + lane];
        float2 f2 = F2[u2 * 32 + lane];
        float2 f3 = F2[u3 * 32 + lane];
        ax += d0 * f0.x; ay += d0 * f0.y;
        ax += d1 * f1.x; ay += d1 * f1.y;
        ax += d2 * f2.x; ay += d2 * f2.y;
        ax += d3 * f3.x; ay += d3 * f3.y;
    }
    for (; e < end; e++) {
        int u = g_col[e];
        float d = g_dinv[u];
        float2 f = F2[u * 32 + lane];
        ax += d * f.x; ay += d * f.y;
    }
}

// kstep = 1..5 : g_F[kstep] = P g_F[kstep-1]
__global__ __launch_bounds__(256) void k_prop(int kstep) {
    int gw = (blockIdx.x * blockDim.x + threadIdx.x) >> 5;
    if (gw >= N_NODES) return;
    int lane = threadIdx.x & 31;
    const float2* Fin  = (const float2*)&g_F[kstep - 1][0];
    float2*       Fout = (float2*)&g_F[kstep][0];
    float ax = 0.f, ay = 0.f;
    prop_accum(g_rowptr[gw], g_rowptr[gw + 1], lane, Fin, ax, ay);
    float dv = g_dinv[gw];
    float2 fv = Fin[gw * 32 + lane];
    fv.x -= dv * ax;
    fv.y -= dv * ay;
    Fout[gw * 32 + lane] = fv;
}

// Final step (k=6) fused with combine: f6 stays in registers.
__global__ __launch_bounds__(256) void k_prop_last(float* __restrict__ out, ThetaPack tp) {
    int gw = (blockIdx.x * blockDim.x + threadIdx.x) >> 5;
    if (gw >= N_NODES) return;
    int lane = threadIdx.x & 31;
    const float2* F5 = (const float2*)&g_F[5][0];
    float ax = 0.f, ay = 0.f;
    prop_accum(g_rowptr[gw], g_rowptr[gw + 1], lane, F5, ax, ay);
    float dv = g_dinv[gw];
    float2 f6 = F5[gw * 32 + lane];
    f6.x -= dv * ax;
    f6.y -= dv * ay;

    float2 f[6];
    #pragma unroll
    for (int k = 0; k < 6; k++)
        f[k] = ((const float2*)&g_F[k][0])[gw * 32 + lane];

    float2* ob = (float2*)(out + (size_t)gw * (5 * H_FEATS)) + lane;
    #pragma unroll
    for (int i = 0; i < 5; i++) {
        float2 a;
        a.x = tp.t[i][6] * f6.x;
        a.y = tp.t[i][6] * f6.y;
        #pragma unroll
        for (int k = 0; k < 6; k++) {
            float c = tp.t[i][k];
            a.x += c * f[k].x;
            a.y += c * f[k].y;
        }
        ob[i * 32] = a;
    }
}

// ---------------- host: theta coefficients ----------------
static double fact_d(int n) { double r = 1.0; for (int i = 2; i <= n; i++) r *= i; return r; }

static ThetaPack make_thetas() {
    ThetaPack tp;
    const int d = 4, OFF = 2;
    const double e = 1.4;
    for (int ii = 0; ii < 5; ii++) {
        int i = OFF + ii;
        int m = d - i + OFF;
        double B = fact_d(i) * fact_d(d - i + OFF) / fact_d(d + 1 + OFF);
        double c[7] = {0, 0, 0, 0, 0, 0, 0};
        double inv_e_i = pow(1.0 / e, (double)i);
        double pj = 1.0;
        for (int j = 0; j <= m; j++) {
            double comb = fact_d(m) / (fact_d(j) * fact_d(m - j));
            c[i + j] = inv_e_i * comb * pj / (e * B);
            pj *= (-1.0 / e);
        }
        for (int k = 0; k < 7; k++) tp.t[ii][k] = (float)c[k];
    }
    return tp;
}

// ---------------- entry point ----------------
extern "C" void kernel_launch(void* const* d_in, const int* in_sizes, int n_in,
                              void* d_out, int out_size) {
    (void)in_sizes; (void)n_in; (void)out_size;
    const float* x   = (const float*)d_in[0];
    const float* W   = (const float*)d_in[1];
    const float* b   = (const float*)d_in[2];
    const int*   src = (const int*)d_in[3];
    const int*   dst = (const int*)d_in[4];
    float* out = (float*)d_out;

    ThetaPack tp = make_thetas();

    // Lazily create the fork stream/events on the FIRST call (the uncaptured
    // correctness run). No device memory is allocated. Subsequent captured
    // calls reuse the handles; the fork/join becomes a parallel graph branch.
    static cudaStream_t s_gemm = 0;
    static cudaEvent_t  ev_fork = 0, ev_join = 0;
    if (s_gemm == 0) {
        cudaStreamCreateWithFlags(&s_gemm, cudaStreamNonBlocking);
        cudaEventCreateWithFlags(&ev_fork, cudaEventDisableTiming);
        cudaEventCreateWithFlags(&ev_join, cudaEventDisableTiming);
    }

    // Fork: GEMM (x,W,b -> g_F[0]) runs concurrently with the CSR chain.
    bool forked = (s_gemm != 0 && ev_fork != 0 && ev_join != 0);
    if (forked) {
        cudaEventRecord(ev_fork, 0);
        cudaStreamWaitEvent(s_gemm, ev_fork, 0);
        k_gemm<<<(N_NODES + 127) / 128, 256, 0, s_gemm>>>(x, W, b);
        cudaEventRecord(ev_join, s_gemm);
    } else {
        k_gemm<<<(N_NODES + 127) / 128, 256>>>(x, W, b);
    }

    // CSR chain on the main stream (counters zeroed: .bss at load, then by k_scatter)
    k_hist<<<(N_EDGES + 255) / 256, 256>>>(src, dst);   // also captures per-edge rank
    k_scan_blk<<<SCAN_NBLK, 1024>>>();
    k_scan_add<<<SCAN_NBLK, 1024>>>();                  // top-scan fused + d_inv
    k_scatter<<<(N_EDGES / 4 + 255) / 256, 256>>>(src, dst);  // atomic-free + counter reset

    // Join: prop needs both g_F[0] (gemm) and CSR.
    if (forked) cudaStreamWaitEvent(0, ev_join, 0);

    // f_k = P^k h, k = 1..5
    int nblk = (N_NODES + 7) / 8;
    for (int k = 1; k <= 5; k++)
        k_prop<<<nblk, 256>>>(k);

    // step 6 fused with combine (f6 never hits memory)
    k_prop_last<<<nblk, 256>>>(out, tp);
}